// round 17
// baseline (speedup 1.0000x reference)
#include <cuda_runtime.h>

#define Bb 4
#define Ll 1024
#define Hh 128
#define Ee 128
#define Nn 128
#define ML (Bb*Ll)   // 4096
#define CH 64        // number of L-chunks
#define CS 16        // chunk size (CH*CS == Ll)
#define CG 16        // chain batch group size

// ---------------- scratch (device globals: no allocations allowed) ----------------
__device__ float g_zs[Bb*Ll*Ee];     // silu(z)
__device__ float g_xc[Bb*Ll*Ee];     // post-conv silu(x)
__device__ float g_delta[Bb*Ll*Nn];  // softplus'd
__device__ float g_Braw[Bb*Ll*Nn];
__device__ float g_C[Bb*Ll*Hh];
__device__ float g_y[Bb*Ll*Hh];      // gated scan output (input to GEMM3)
__device__ float g_S[Bb*Ll*Hh];      // local (then full) n-sums
__device__ float g_cumd[Bb*Ll*Nn];   // within-chunk inclusive cumsum of delta
__device__ float g_hE[Bb*CH*Nn*Hh]; // chunk-end local states [b][k][n][c]
__device__ float g_h0[Bb*CH*Nn*Hh]; // chunk-start true states [b][k][n][c]

__device__ __forceinline__ float silu_(float x){ return x / (1.f + __expf(-x)); }
__device__ __forceinline__ float softplus_(float x){ return x > 20.f ? x : log1pf(__expf(x)); }
__device__ __forceinline__ float ex2f(float x){ float r; asm("ex2.approx.ftz.f32 %0, %1;" : "=f"(r) : "f"(x)); return r; }

// ---------------- GEMM1: xz = u @ W_in + b_in, conv3+silu fused in epilogue --------
// x-blocks (col0 < 128) write g_xc directly (conv kernel + g_x eliminated);
// z-blocks write g_zs = silu(z). Register-prefetch double buffering as in R16.
__global__ __launch_bounds__(256) void gemm1_kernel(
    const float* __restrict__ u, const float* __restrict__ Wp,
    const float* __restrict__ bias,
    const float* __restrict__ cw, const float* __restrict__ cb)
{
    __shared__ __align__(16) float pool[64 * 68 + 64 * 64];   // As | Bs, later xt
    __shared__ __align__(16) float su[2][128];
    float (*As)[68] = (float(*)[68])pool;
    float (*Bs)[64] = (float(*)[64])(pool + 64 * 68);
    const int ldN = 256;

    int tid = threadIdx.x;
    int ty = tid >> 4, tx = tid & 15;
    int row0 = blockIdx.x * 64;
    int col0 = blockIdx.y * 64;

    float acc[4][4];
    #pragma unroll
    for (int i = 0; i < 4; i++)
        #pragma unroll
        for (int j = 0; j < 4; j++) acc[i][j] = 0.f;

    float4 pA[4], pB[4];
    #pragma unroll
    for (int i = 0; i < 4; ++i) {
        int f = tid + i * 256;
        int r = f >> 4, kq = f & 15;
        pA[i] = *(const float4*)&u[(size_t)(row0 + r) * 128 + kq * 4];
    }
    #pragma unroll
    for (int i = 0; i < 4; ++i) {
        int f = tid + i * 256;
        int k = f >> 4, nq = f & 15;
        pB[i] = *(const float4*)&Wp[(size_t)k * ldN + col0 + nq * 4];
    }

    #pragma unroll
    for (int kb = 0; kb < 2; ++kb) {
        #pragma unroll
        for (int i = 0; i < 4; ++i) {
            int f = tid + i * 256;
            int r = f >> 4, kq = f & 15;
            *(float4*)&As[r][kq * 4] = pA[i];
        }
        #pragma unroll
        for (int i = 0; i < 4; ++i) {
            int f = tid + i * 256;
            int k = f >> 4, nq = f & 15;
            *(float4*)&Bs[k][nq * 4] = pB[i];
        }
        __syncthreads();
        if (kb == 0) {
            #pragma unroll
            for (int i = 0; i < 4; ++i) {
                int f = tid + i * 256;
                int r = f >> 4, kq = f & 15;
                pA[i] = *(const float4*)&u[(size_t)(row0 + r) * 128 + 64 + kq * 4];
            }
            #pragma unroll
            for (int i = 0; i < 4; ++i) {
                int f = tid + i * 256;
                int k = f >> 4, nq = f & 15;
                pB[i] = *(const float4*)&Wp[(size_t)(64 + k) * ldN + col0 + nq * 4];
            }
        }
        #pragma unroll 16
        for (int k = 0; k < 64; ++k) {
            float4 bv = *(float4*)&Bs[k][tx * 4];
            float a0 = As[ty * 4 + 0][k];
            float a1 = As[ty * 4 + 1][k];
            float a2 = As[ty * 4 + 2][k];
            float a3 = As[ty * 4 + 3][k];
            acc[0][0] = fmaf(a0, bv.x, acc[0][0]); acc[0][1] = fmaf(a0, bv.y, acc[0][1]);
            acc[0][2] = fmaf(a0, bv.z, acc[0][2]); acc[0][3] = fmaf(a0, bv.w, acc[0][3]);
            acc[1][0] = fmaf(a1, bv.x, acc[1][0]); acc[1][1] = fmaf(a1, bv.y, acc[1][1]);
            acc[1][2] = fmaf(a1, bv.z, acc[1][2]); acc[1][3] = fmaf(a1, bv.w, acc[1][3]);
            acc[2][0] = fmaf(a2, bv.x, acc[2][0]); acc[2][1] = fmaf(a2, bv.y, acc[2][1]);
            acc[2][2] = fmaf(a2, bv.z, acc[2][2]); acc[2][3] = fmaf(a2, bv.w, acc[2][3]);
            acc[3][0] = fmaf(a3, bv.x, acc[3][0]); acc[3][1] = fmaf(a3, bv.y, acc[3][1]);
            acc[3][2] = fmaf(a3, bv.z, acc[3][2]); acc[3][3] = fmaf(a3, bv.w, acc[3][3]);
        }
        __syncthreads();
    }

    if (col0 >= 128) {
        // z epilogue: silu gate
        #pragma unroll
        for (int i = 0; i < 4; ++i) {
            int row = row0 + ty * 4 + i;
            #pragma unroll
            for (int j = 0; j < 4; ++j) {
                int col = col0 + tx * 4 + j;
                g_zs[(size_t)row * 128 + col - 128] = silu_(acc[i][j] + bias[col]);
            }
        }
        return;
    }

    // ---- x epilogue: conv3 + silu -> g_xc (pool is dead; reuse as xt[66][68]) ----
    float (*xt)[68] = (float(*)[68])pool;
    int t0 = row0 & (Ll - 1);

    // stage u halo rows (zeros at sequence boundaries)
    if (tid < 128) {
        su[0][tid] = (t0 > 0) ? u[(size_t)(row0 - 1) * 128 + tid] : 0.f;
    } else {
        int q = tid - 128;
        su[1][q] = (t0 + 64 < Ll) ? u[(size_t)(row0 + 64) * 128 + q] : 0.f;
    }
    // write x tile (+bias) into xt rows 1..64
    {
        int colb = col0 + tx * 4;
        float4 bv4 = *(const float4*)&bias[colb];
        #pragma unroll
        for (int i = 0; i < 4; ++i) {
            float4 v;
            v.x = acc[i][0] + bv4.x; v.y = acc[i][1] + bv4.y;
            v.z = acc[i][2] + bv4.z; v.w = acc[i][3] + bv4.w;
            *(float4*)&xt[1 + ty * 4 + i][tx * 4] = v;
        }
    }
    __syncthreads();

    // halo x rows via dot products (tid<64: top row -> xt[0]; 64..127: bottom -> xt[65])
    if (tid < 128) {
        int which = tid >> 6;
        int cl = tid & 63;
        int c = col0 + cl;
        bool valid = which ? (t0 + 64 < Ll) : (t0 > 0);
        float s0 = 0.f, s1 = 0.f;
        #pragma unroll 8
        for (int k = 0; k < 128; k += 2) {
            s0 = fmaf(su[which][k],     Wp[(size_t)k * ldN + c],       s0);
            s1 = fmaf(su[which][k + 1], Wp[(size_t)(k + 1) * ldN + c], s1);
        }
        xt[which ? 65 : 0][cl] = valid ? (s0 + s1 + bias[c]) : 0.f;
    }
    __syncthreads();

    // conv3 + silu, write g_xc
    {
        float w0[4], w1[4], w2[4], cbv[4];
        #pragma unroll
        for (int j = 0; j < 4; ++j) {
            int e = col0 + tx * 4 + j;
            w0[j] = cw[e * 3 + 0]; w1[j] = cw[e * 3 + 1]; w2[j] = cw[e * 3 + 2];
            cbv[j] = cb[e];
        }
        #pragma unroll
        for (int i = 0; i < 4; ++i) {
            int rl = ty * 4 + i;
            int row = row0 + rl;
            float4 a = *(float4*)&xt[rl][tx * 4];
            float4 m = *(float4*)&xt[rl + 1][tx * 4];
            float4 r = *(float4*)&xt[rl + 2][tx * 4];
            float av[4] = {a.x, a.y, a.z, a.w};
            float mv[4] = {m.x, m.y, m.z, m.w};
            float rv[4] = {r.x, r.y, r.z, r.w};
            float4 o;
            float* op = &o.x;
            #pragma unroll
            for (int j = 0; j < 4; ++j) {
                float v = fmaf(w0[j], av[j], fmaf(w1[j], mv[j], fmaf(w2[j], rv[j], cbv[j])));
                op[j] = silu_(v);
            }
            *(float4*)&g_xc[(size_t)row * 128 + col0 + tx * 4] = o;
        }
    }
}

// ---------------- generic 64x64-tile SGEMM (EPI 2,3), register prefetch ------------
template<int EPI>
__global__ __launch_bounds__(256) void gemm_kernel(
    const float* __restrict__ Ain, const float* __restrict__ Wp,
    const float* __restrict__ bias, float* __restrict__ Cout, int ldN)
{
    __shared__ __align__(16) float As[64][68];   // [row][k]
    __shared__ __align__(16) float Bs[64][64];   // [k][col]
    const float* Ap = (EPI == 2) ? g_xc : g_y;
    (void)Ain;

    int tid = threadIdx.x;
    int ty = tid >> 4, tx = tid & 15;
    int row0 = blockIdx.x * 64;
    int col0 = blockIdx.y * 64;

    float acc[4][4];
    #pragma unroll
    for (int i = 0; i < 4; i++)
        #pragma unroll
        for (int j = 0; j < 4; j++) acc[i][j] = 0.f;

    float4 pA[4], pB[4];
    #pragma unroll
    for (int i = 0; i < 4; ++i) {
        int f = tid + i * 256;
        int r = f >> 4, kq = f & 15;
        pA[i] = *(const float4*)&Ap[(size_t)(row0 + r) * 128 + kq * 4];
    }
    #pragma unroll
    for (int i = 0; i < 4; ++i) {
        int f = tid + i * 256;
        int k = f >> 4, nq = f & 15;
        pB[i] = *(const float4*)&Wp[(size_t)k * ldN + col0 + nq * 4];
    }

    #pragma unroll
    for (int kb = 0; kb < 2; ++kb) {
        #pragma unroll
        for (int i = 0; i < 4; ++i) {
            int f = tid + i * 256;
            int r = f >> 4, kq = f & 15;
            *(float4*)&As[r][kq * 4] = pA[i];
        }
        #pragma unroll
        for (int i = 0; i < 4; ++i) {
            int f = tid + i * 256;
            int k = f >> 4, nq = f & 15;
            *(float4*)&Bs[k][nq * 4] = pB[i];
        }
        __syncthreads();
        if (kb == 0) {
            #pragma unroll
            for (int i = 0; i < 4; ++i) {
                int f = tid + i * 256;
                int r = f >> 4, kq = f & 15;
                pA[i] = *(const float4*)&Ap[(size_t)(row0 + r) * 128 + 64 + kq * 4];
            }
            #pragma unroll
            for (int i = 0; i < 4; ++i) {
                int f = tid + i * 256;
                int k = f >> 4, nq = f & 15;
                pB[i] = *(const float4*)&Wp[(size_t)(64 + k) * ldN + col0 + nq * 4];
            }
        }
        #pragma unroll 16
        for (int k = 0; k < 64; ++k) {
            float4 bv = *(float4*)&Bs[k][tx * 4];
            float a0 = As[ty * 4 + 0][k];
            float a1 = As[ty * 4 + 1][k];
            float a2 = As[ty * 4 + 2][k];
            float a3 = As[ty * 4 + 3][k];
            acc[0][0] = fmaf(a0, bv.x, acc[0][0]); acc[0][1] = fmaf(a0, bv.y, acc[0][1]);
            acc[0][2] = fmaf(a0, bv.z, acc[0][2]); acc[0][3] = fmaf(a0, bv.w, acc[0][3]);
            acc[1][0] = fmaf(a1, bv.x, acc[1][0]); acc[1][1] = fmaf(a1, bv.y, acc[1][1]);
            acc[1][2] = fmaf(a1, bv.z, acc[1][2]); acc[1][3] = fmaf(a1, bv.w, acc[1][3]);
            acc[2][0] = fmaf(a2, bv.x, acc[2][0]); acc[2][1] = fmaf(a2, bv.y, acc[2][1]);
            acc[2][2] = fmaf(a2, bv.z, acc[2][2]); acc[2][3] = fmaf(a2, bv.w, acc[2][3]);
            acc[3][0] = fmaf(a3, bv.x, acc[3][0]); acc[3][1] = fmaf(a3, bv.y, acc[3][1]);
            acc[3][2] = fmaf(a3, bv.z, acc[3][2]); acc[3][3] = fmaf(a3, bv.w, acc[3][3]);
        }
        __syncthreads();
    }

    #pragma unroll
    for (int i = 0; i < 4; ++i) {
        int row = row0 + ty * 4 + i;
        #pragma unroll
        for (int j = 0; j < 4; ++j) {
            int col = col0 + tx * 4 + j;
            float v = acc[i][j] + bias[col];
            if (EPI == 2) {
                if (col < 128)      g_delta[(size_t)row * 128 + col] = softplus_(v);
                else if (col < 256) g_Braw[(size_t)row * 128 + col - 128] = v;
                else                g_C[(size_t)row * 128 + col - 256] = v;
            } else {
                Cout[(size_t)row * 128 + col] = v;
            }
        }
    }
}

// ---------------- Pass 1: per-chunk local scan (4n x 4c states per thread) ----------
__global__ __launch_bounds__(256) void scan_local_kernel(const float* __restrict__ A_log)
{
    __shared__ __align__(16) float smd[16][128];
    __shared__ __align__(16) float smb[16][128];
    __shared__ __align__(16) float smx[16][32];
    __shared__ float smP[4][32][33];

    int b  = blockIdx.z;
    int k  = blockIdx.y;
    int cg = blockIdx.x;
    int tid = threadIdx.x;
    int w = tid >> 5, ln = tid & 31;

    float Ac2[4];
    #pragma unroll
    for (int j = 0; j < 4; ++j)
        Ac2[j] = -__expf(A_log[cg * 32 + w * 4 + j]) * 1.44269504f;

    const float4* del4 = (const float4*)(g_delta + (size_t)b * Ll * Nn);
    const float4* br4  = (const float4*)(g_Braw  + (size_t)b * Ll * Nn);
    const float* xcb   = g_xc + (size_t)b * Ll * Ee + cg * 32;

    float h[4][4];
    #pragma unroll
    for (int j = 0; j < 4; ++j)
        #pragma unroll
        for (int i = 0; i < 4; ++i) h[j][i] = 0.f;

    float dc = 0.f;
    bool do_cum = (cg == 0) && (tid < 128);

    for (int t0 = k * CS; t0 < (k + 1) * CS; t0 += 16) {
        #pragma unroll
        for (int i = 0; i < 2; ++i) {
            int idx = tid + i * 256;
            float4 d = del4[t0 * 32 + idx];
            float4 r = br4[t0 * 32 + idx];
            ((float4*)smd)[idx] = d;
            float4 p; p.x = d.x * r.x; p.y = d.y * r.y; p.z = d.z * r.z; p.w = d.w * r.w;
            ((float4*)smb)[idx] = p;
        }
        if (tid < 128) {
            int tt = tid >> 3, q = tid & 7;
            *(float4*)&smx[tt][q * 4] = *(const float4*)&xcb[(size_t)(t0 + tt) * Ee + q * 4];
        }
        __syncthreads();

        if (do_cum) {
            float* gout = g_cumd + (size_t)b * Ll * Nn + (size_t)t0 * Nn + tid;
            #pragma unroll
            for (int tl = 0; tl < 16; ++tl) { dc += smd[tl][tid]; gout[tl * 128] = dc; }
        }

        #pragma unroll
        for (int tb = 0; tb < 16; tb += 4) {
            #pragma unroll
            for (int tt = 0; tt < 4; ++tt) {
                int t = tb + tt;
                float4 d4 = *(float4*)&smd[t][ln * 4];
                float4 b4 = *(float4*)&smb[t][ln * 4];
                float4 x4 = *(float4*)&smx[t][w * 4];
                float dn[4] = {d4.x, d4.y, d4.z, d4.w};
                float bn[4] = {b4.x, b4.y, b4.z, b4.w};
                float xs[4] = {x4.x, x4.y, x4.z, x4.w};
                #pragma unroll
                for (int j = 0; j < 4; ++j) {
                    #pragma unroll
                    for (int i = 0; i < 4; ++i) {
                        float e = ex2f(dn[i] * Ac2[j]);
                        h[j][i] = fmaf(e, h[j][i], bn[i] * xs[j]);
                    }
                    smP[tt][ln][w * 4 + j] = (h[j][0] + h[j][1]) + (h[j][2] + h[j][3]);
                }
            }
            __syncthreads();
            if (tid < 128) {
                int tt = tid >> 5, c = tid & 31;
                float s = 0.f;
                #pragma unroll
                for (int q = 0; q < 32; ++q) s += smP[tt][q][c];
                int t = t0 + tb + tt;
                g_S[(size_t)b * Ll * Hh + (size_t)t * Hh + cg * 32 + c] = s;
            }
            __syncthreads();
        }
    }

    size_t base = ((size_t)(b * CH + k) * Nn + ln * 4) * Hh + cg * 32 + w * 4;
    #pragma unroll
    for (int i = 0; i < 4; ++i) {
        float4 v; v.x = h[0][i]; v.y = h[1][i]; v.z = h[2][i]; v.w = h[3][i];
        *(float4*)&g_hE[base + (size_t)i * Hh] = v;
    }
}

// ---------------- Pass 2: inter-chunk state chain (grouped batched loads) ----------
__global__ __launch_bounds__(256) void chain_kernel(const float* __restrict__ A_log)
{
    int g = blockIdx.x * 256 + threadIdx.x;        // 0 .. 65535
    int c = g & 127, n = (g >> 7) & 127, b = g >> 14;
    float Ac2 = -__expf(A_log[c]) * 1.44269504f;
    const float* cd = g_cumd + (size_t)b * Ll * Nn + n;
    size_t base = ((size_t)(b * CH) * Nn + n) * Hh + c;   // k stride = Nn*Hh

    float h = 0.f;
    #pragma unroll
    for (int grp = 0; grp < CH / CG; ++grp) {
        int k0 = grp * CG;
        float dec[CG], hE[CG];
        #pragma unroll
        for (int k = 0; k < CG; ++k)
            dec[k] = cd[(size_t)((k0 + k) * CS + CS - 1) * Nn];
        #pragma unroll
        for (int k = 0; k < CG; ++k)
            hE[k] = g_hE[base + (size_t)(k0 + k) * (Nn * Hh)];
        #pragma unroll
        for (int k = 0; k < CG; ++k)
            dec[k] = ex2f(Ac2 * dec[k]);
        #pragma unroll
        for (int k = 0; k < CG; ++k) {
            g_h0[base + (size_t)(k0 + k) * (Nn * Hh)] = h;
            h = fmaf(dec[k], h, hE[k]);
        }
    }
}

// ---------------- Pass 3: fixup + combine ----------------
#define T3 8
__global__ __launch_bounds__(256) void fixup_kernel(
    const float* __restrict__ A_log, const float* __restrict__ Dv,
    const float* __restrict__ u)
{
    __shared__ __align__(16) float smh[32][128];
    __shared__ __align__(16) float smc[T3][128];

    int b = blockIdx.z, k = blockIdx.y, tg = blockIdx.x;
    int t0 = k * CS + tg * T3;
    int tid = threadIdx.x;
    int c = tid & 127, th = tid >> 7;

    float acc[4] = {0.f, 0.f, 0.f, 0.f};

    if (k > 0) {
        float Ac2 = -__expf(A_log[c]) * 1.44269504f;
        #pragma unroll
        for (int i = 0; i < 4; ++i) {
            int idx = tid + i * 256;
            int tt = idx >> 7, n = idx & 127;
            smc[tt][n] = g_cumd[(size_t)b * Ll * Nn + (size_t)(t0 + tt) * Nn + n];
        }
        const float4* h0p = (const float4*)(g_h0 + ((size_t)(b * CH + k) * Nn) * Hh);
        #pragma unroll
        for (int nb = 0; nb < 4; ++nb) {
            __syncthreads();
            #pragma unroll
            for (int i = 0; i < 4; ++i) {
                int idx = tid + i * 256;
                ((float4*)smh)[idx] = h0p[nb * 1024 + idx];
            }
            __syncthreads();
            #pragma unroll
            for (int n = 0; n < 32; ++n) {
                float hv = smh[n][c];
                #pragma unroll
                for (int j = 0; j < 4; ++j) {
                    float dl = smc[th * 4 + j][nb * 32 + n];
                    acc[j] = fmaf(ex2f(dl * Ac2), hv, acc[j]);
                }
            }
        }
    }

    #pragma unroll
    for (int j = 0; j < 4; ++j) {
        int t = t0 + th * 4 + j;
        size_t off = (size_t)b * Ll * Hh + (size_t)t * Hh + c;
        float S = g_S[off] + acc[j];
        float y = fmaf(S, g_C[off], Dv[c] * u[off]);
        g_y[off] = y * g_zs[off];
    }
}

// ---------------- launch ----------------
extern "C" void kernel_launch(void* const* d_in, const int* in_sizes, int n_in,
                              void* d_out, int out_size)
{
    const float* u      = (const float*)d_in[0];
    const float* W_in   = (const float*)d_in[1];
    const float* b_in   = (const float*)d_in[2];
    const float* conv_w = (const float*)d_in[3];
    const float* conv_b = (const float*)d_in[4];
    const float* W_x    = (const float*)d_in[5];
    const float* b_x    = (const float*)d_in[6];
    const float* A_log  = (const float*)d_in[7];
    const float* Dv     = (const float*)d_in[8];
    const float* W_out  = (const float*)d_in[9];
    const float* b_out  = (const float*)d_in[10];
    float* out = (float*)d_out;

    dim3 blk(256);
    gemm1_kernel<<<dim3(ML / 64, 256 / 64), blk>>>(u, W_in, b_in, conv_w, conv_b);
    gemm_kernel<2><<<dim3(ML / 64, 384 / 64), blk>>>(nullptr, W_x, b_x, nullptr, 384);
    scan_local_kernel<<<dim3(4, CH, Bb), blk>>>(A_log);
    chain_kernel<<<dim3(Bb * Nn * Hh / 256), blk>>>(A_log);
    fixup_kernel<<<dim3(CS / T3, CH, Bb), blk>>>(A_log, Dv, u);
    gemm_kernel<3><<<dim3(ML / 64, 128 / 64), blk>>>(nullptr, W_out, b_out, out, 128);
}